// round 4
// baseline (speedup 1.0000x reference)
#include <cuda_runtime.h>

#define N_PIX 4096
#define DIMC  256
#define HID   512
#define EPSB  1e-5f
#define PADV  66
#define PADI  132

// scratch (no cudaMalloc allowed)
__device__ float g_qkv[2 * HID * N_PIX];   // 16 MB
__device__ float g_y[2 * DIMC * N_PIX];    //  8 MB

typedef unsigned long long u64;

__device__ __forceinline__ u64 pk2(float lo, float hi) {
    u64 r; asm("mov.b64 %0, {%1, %2};" : "=l"(r) : "f"(lo), "f"(hi)); return r;
}
__device__ __forceinline__ void fma2(u64& d, u64 a, u64 b) {
    asm("fma.rn.f32x2 %0, %1, %2, %0;" : "+l"(d) : "l"(a), "l"(b));
}
__device__ __forceinline__ u64 mul2(u64 a, u64 b) {
    u64 r; asm("mul.rn.f32x2 %0, %1, %2;" : "=l"(r) : "l"(a), "l"(b)); return r;
}
__device__ __forceinline__ float2 up2(u64 a) {
    float2 f; asm("mov.b64 {%0, %1}, %2;" : "=f"(f.x), "=f"(f.y) : "l"(a)); return f;
}

// ---------------------------------------------------------------------------
// GEMM + folded BatchNorm:  out[m][n] = (sum_k W[m][k] X[k][n]) * s[m] + bias[m]
// BM=BN=64, BK=16, 256 threads, 4x4 microtile. K is always 256 (DIMC).
// ---------------------------------------------------------------------------
__global__ void __launch_bounds__(256)
gemm_bn(const float* __restrict__ W, const float* __restrict__ X,
        const float* __restrict__ gg, const float* __restrict__ bb,
        const float* __restrict__ mm, const float* __restrict__ vv,
        float* __restrict__ out, int M)
{
    __shared__ float Ws[16][68];
    __shared__ float Xs[16][68];
    const float* Xb = X + (size_t)blockIdx.z * DIMC * N_PIX;
    float* outb = out + (size_t)blockIdx.z * M * N_PIX;
    const int m0 = blockIdx.y * 64, n0 = blockIdx.x * 64;
    const int tid = threadIdx.x;
    const int tm = tid >> 4, tn = tid & 15;
    float acc[4][4] = {};

    for (int k0 = 0; k0 < DIMC; k0 += 16) {
        {
            int r = tid >> 2, c = (tid & 3) * 4;
            float4 wv = *(const float4*)(W + (size_t)(m0 + r) * DIMC + k0 + c);
            Ws[c + 0][r] = wv.x; Ws[c + 1][r] = wv.y;
            Ws[c + 2][r] = wv.z; Ws[c + 3][r] = wv.w;
            int r2 = tid >> 4, c2 = (tid & 15) * 4;
            float4 xv = *(const float4*)(Xb + (size_t)(k0 + r2) * N_PIX + n0 + c2);
            *(float4*)&Xs[r2][c2] = xv;
        }
        __syncthreads();
        #pragma unroll
        for (int k = 0; k < 16; k++) {
            float a4[4], b4[4];
            *(float4*)a4 = *(const float4*)&Ws[k][tm * 4];
            *(float4*)b4 = *(const float4*)&Xs[k][tn * 4];
            #pragma unroll
            for (int i = 0; i < 4; i++)
                #pragma unroll
                for (int j = 0; j < 4; j++)
                    acc[i][j] = fmaf(a4[i], b4[j], acc[i][j]);
        }
        __syncthreads();
    }
    #pragma unroll
    for (int i = 0; i < 4; i++) {
        int m = m0 + tm * 4 + i;
        float s = gg[m] * rsqrtf(vv[m] + EPSB);
        float bias = bb[m] - mm[m] * s;
        float4 o;
        o.x = acc[i][0] * s + bias; o.y = acc[i][1] * s + bias;
        o.z = acc[i][2] * s + bias; o.w = acc[i][3] * s + bias;
        *(float4*)(outb + (size_t)m * N_PIX + n0 + tn * 4) = o;
    }
}

// ---------------------------------------------------------------------------
// Flash attention, fp32 with packed f32x2 FMA.
// One CTA per (b,h, 128-query tile). q/k: 32 x N, v: 64 x N.
// pass1: S-tile 128x128 in registers (j paired), online softmax -> P in smem
//        transposed [j][i] (row pad PADI).
// pass2: y[i][d] += P * V^T with V transposed in smem [j][d] (row pad PADV),
//        accumulators paired over d.
// ---------------------------------------------------------------------------
__global__ void __launch_bounds__(256, 1)
attn_kernel(const float* __restrict__ qkv, float* __restrict__ ybuf)
{
    extern __shared__ float smf[];
    float* q_s    = smf;                    // [32][128]
    float* k_s    = q_s + 32 * 128;         // [32][128]
    float* v_t    = k_s + 32 * 128;         // [128][PADV]
    float* p_t    = v_t + 128 * PADV;       // [128][PADI]
    float* corr_s = p_t + 128 * PADI;       // [128]
    float* l_s    = corr_s + 128;           // [128]

    const int tid = threadIdx.x;
    const int bh = blockIdx.y;
    const int bbi = bh >> 2, hh = bh & 3;
    const int i0 = blockIdx.x * 128;
    const float* qp = qkv + ((size_t)bbi * HID + hh * 128) * N_PIX;
    const float* kp = qp + 32 * N_PIX;
    const float* vp = qp + 64 * N_PIX;
    const float qscale = 0.17677669529663687f;   // KEY_DIM^-0.5

    // load q tile, fold softmax scale
    for (int idx = tid * 4; idx < 32 * 128; idx += 1024) {
        int d = idx >> 7, ii = idx & 127;
        float4 q4 = *(const float4*)(qp + (size_t)d * N_PIX + i0 + ii);
        q4.x *= qscale; q4.y *= qscale; q4.z *= qscale; q4.w *= qscale;
        *(float4*)&q_s[d * 128 + ii] = q4;
    }

    const int ty = tid >> 4, tx = tid & 15;    // pass1: i-group / j-group
    const int ig = tid >> 3, dg = tid & 7;     // pass2: i-group / d-group

    float m_i[8], l_i[8];
    #pragma unroll
    for (int u = 0; u < 8; u++) { m_i[u] = -3.0e38f; l_i[u] = 0.f; }
    u64 acc2[4][4];
    #pragma unroll
    for (int a = 0; a < 4; a++)
        #pragma unroll
        for (int c = 0; c < 4; c++) acc2[a][c] = 0ull;

    for (int j0 = 0; j0 < N_PIX; j0 += 128) {
        __syncthreads();   // prev pass2 done with v_t / p_t
        for (int idx = tid * 4; idx < 32 * 128; idx += 1024) {
            int d = idx >> 7, jj = idx & 127;
            *(float4*)&k_s[d * 128 + jj] =
                *(const float4*)(kp + (size_t)d * N_PIX + j0 + jj);
        }
        for (int idx = tid * 4; idx < 64 * 128; idx += 1024) {
            int d = idx >> 7, jj = idx & 127;
            float4 v4 = *(const float4*)(vp + (size_t)d * N_PIX + j0 + jj);
            v_t[(jj + 0) * PADV + d] = v4.x;
            v_t[(jj + 1) * PADV + d] = v4.y;
            v_t[(jj + 2) * PADV + d] = v4.z;
            v_t[(jj + 3) * PADV + d] = v4.w;
        }
        __syncthreads();

        // ---- pass 1: S = q^T k (f32x2 over j pairs) ----
        u64 s2[8][4];
        #pragma unroll
        for (int ii = 0; ii < 8; ii++)
            #pragma unroll
            for (int jp = 0; jp < 4; jp++) s2[ii][jp] = 0ull;

        #pragma unroll 4
        for (int d = 0; d < 32; d++) {
            float4 qa = *(const float4*)&q_s[d * 128 + ty * 8];
            float4 qb = *(const float4*)&q_s[d * 128 + ty * 8 + 4];
            ulonglong2 k01 = *(const ulonglong2*)&k_s[d * 128 + tx * 8];
            ulonglong2 k23 = *(const ulonglong2*)&k_s[d * 128 + tx * 8 + 4];
            float qv[8] = {qa.x, qa.y, qa.z, qa.w, qb.x, qb.y, qb.z, qb.w};
            #pragma unroll
            for (int ii = 0; ii < 8; ii++) {
                u64 qq = pk2(qv[ii], qv[ii]);
                fma2(s2[ii][0], qq, k01.x);
                fma2(s2[ii][1], qq, k01.y);
                fma2(s2[ii][2], qq, k23.x);
                fma2(s2[ii][3], qq, k23.y);
            }
        }

        // ---- online softmax ----
        #pragma unroll
        for (int ii = 0; ii < 8; ii++) {
            float2 sv0 = up2(s2[ii][0]), sv1 = up2(s2[ii][1]);
            float2 sv2 = up2(s2[ii][2]), sv3 = up2(s2[ii][3]);
            float rmax = fmaxf(fmaxf(fmaxf(sv0.x, sv0.y), fmaxf(sv1.x, sv1.y)),
                               fmaxf(fmaxf(sv2.x, sv2.y), fmaxf(sv3.x, sv3.y)));
            #pragma unroll
            for (int off = 1; off < 16; off <<= 1)
                rmax = fmaxf(rmax, __shfl_xor_sync(0xffffffffu, rmax, off));
            float mo = m_i[ii];
            float mn = fmaxf(mo, rmax);
            float corr = __expf(mo - mn);
            int i_loc = ty * 8 + ii;
            float p0 = __expf(sv0.x - mn), p1 = __expf(sv0.y - mn);
            float p2 = __expf(sv1.x - mn), p3 = __expf(sv1.y - mn);
            float p4 = __expf(sv2.x - mn), p5 = __expf(sv2.y - mn);
            float p6 = __expf(sv3.x - mn), p7 = __expf(sv3.y - mn);
            float rsum = ((p0 + p1) + (p2 + p3)) + ((p4 + p5) + (p6 + p7));
            float* pw = p_t + (tx * 8) * PADI + i_loc;
            pw[0 * PADI] = p0; pw[1 * PADI] = p1;
            pw[2 * PADI] = p2; pw[3 * PADI] = p3;
            pw[4 * PADI] = p4; pw[5 * PADI] = p5;
            pw[6 * PADI] = p6; pw[7 * PADI] = p7;
            #pragma unroll
            for (int off = 1; off < 16; off <<= 1)
                rsum += __shfl_xor_sync(0xffffffffu, rsum, off);
            m_i[ii] = mn;
            l_i[ii] = l_i[ii] * corr + rsum;
            if (tx == 0) corr_s[i_loc] = corr;
        }
        __syncthreads();

        // ---- pass 2: y += P * V^T (f32x2 over d pairs) ----
        {
            u64 cf[4];
            #pragma unroll
            for (int a = 0; a < 4; a++) {
                float c = corr_s[ig * 4 + a];
                cf[a] = pk2(c, c);
            }
            #pragma unroll
            for (int a = 0; a < 4; a++)
                #pragma unroll
                for (int c = 0; c < 4; c++)
                    acc2[a][c] = mul2(acc2[a][c], cf[a]);

            #pragma unroll 4
            for (int j = 0; j < 128; j++) {
                float4 p4 = *(const float4*)&p_t[j * PADI + ig * 4];
                const u64* vq = (const u64*)&v_t[j * PADV + dg * 8];
                u64 v0 = vq[0], v1 = vq[1], v2 = vq[2], v3 = vq[3];
                float pa[4] = {p4.x, p4.y, p4.z, p4.w};
                #pragma unroll
                for (int a = 0; a < 4; a++) {
                    u64 pp = pk2(pa[a], pa[a]);
                    fma2(acc2[a][0], pp, v0);
                    fma2(acc2[a][1], pp, v1);
                    fma2(acc2[a][2], pp, v2);
                    fma2(acc2[a][3], pp, v3);
                }
            }
        }
    }

    if (tx == 0) {
        #pragma unroll
        for (int ii = 0; ii < 8; ii++) l_s[ty * 8 + ii] = l_i[ii];
    }
    __syncthreads();

    float* yb = ybuf + ((size_t)bbi * DIMC + hh * 64) * N_PIX + i0;
    #pragma unroll
    for (int a = 0; a < 4; a++) {
        float linv = 1.0f / l_s[ig * 4 + a];
        #pragma unroll
        for (int c = 0; c < 4; c++) {
            float2 f = up2(acc2[a][c]);
            int d0 = dg * 8 + c * 2;
            yb[(size_t)(d0 + 0) * N_PIX + ig * 4 + a] = f.x * linv;
            yb[(size_t)(d0 + 1) * N_PIX + ig * 4 + a] = f.y * linv;
        }
    }
}

// ---------------------------------------------------------------------------
// Depthwise 3x3 conv on V + BN, accumulated into ybuf (y = attn_out + pe).
// One CTA per (b, c). V channel c maps to qkv channel (c/64)*128 + 64 + c%64.
// ---------------------------------------------------------------------------
__global__ void __launch_bounds__(256)
pe_kernel(const float* __restrict__ qkv, const float* __restrict__ pw,
          const float* __restrict__ gg, const float* __restrict__ bb,
          const float* __restrict__ mm, const float* __restrict__ vv,
          float* __restrict__ ybuf)
{
    int bc = blockIdx.x;
    int b = bc >> 8, c = bc & 255;
    const float* vsrc = qkv + ((size_t)b * HID + (c >> 6) * 128 + 64 + (c & 63)) * N_PIX;
    float w[9];
    #pragma unroll
    for (int t = 0; t < 9; t++) w[t] = pw[c * 9 + t];
    float s = gg[c] * rsqrtf(vv[c] + EPSB);
    float bias = bb[c] - mm[c] * s;
    float* yp = ybuf + ((size_t)b * DIMC + c) * N_PIX;
    for (int p = threadIdx.x; p < N_PIX; p += 256) {
        int yy = p >> 6, xx = p & 63;
        float acc = 0.f;
        #pragma unroll
        for (int ky = 0; ky < 3; ky++) {
            int y2 = yy + ky - 1;
            if (y2 < 0 || y2 > 63) continue;
            #pragma unroll
            for (int kx = 0; kx < 3; kx++) {
                int x2 = xx + kx - 1;
                if (x2 < 0 || x2 > 63) continue;
                acc = fmaf(w[ky * 3 + kx], vsrc[y2 * 64 + x2], acc);
            }
        }
        yp[p] += acc * s + bias;
    }
}

// ---------------------------------------------------------------------------
extern "C" void kernel_launch(void* const* d_in, const int* in_sizes, int n_in,
                              void* d_out, int out_size)
{
    (void)in_sizes; (void)n_in; (void)out_size;
    const float* x      = (const float*)d_in[0];
    const float* qkv_w  = (const float*)d_in[1];
    const float* qkv_g  = (const float*)d_in[2];
    const float* qkv_b  = (const float*)d_in[3];
    const float* qkv_m  = (const float*)d_in[4];
    const float* qkv_v  = (const float*)d_in[5];
    const float* proj_w = (const float*)d_in[6];
    const float* proj_g = (const float*)d_in[7];
    const float* proj_b = (const float*)d_in[8];
    const float* proj_m = (const float*)d_in[9];
    const float* proj_v = (const float*)d_in[10];
    const float* pe_w   = (const float*)d_in[11];
    const float* pe_g   = (const float*)d_in[12];
    const float* pe_b   = (const float*)d_in[13];
    const float* pe_m   = (const float*)d_in[14];
    const float* pe_v   = (const float*)d_in[15];
    float* out = (float*)d_out;

    void* pq = nullptr; void* py = nullptr;
    cudaGetSymbolAddress(&pq, g_qkv);
    cudaGetSymbolAddress(&py, g_y);
    float* qkvb = (float*)pq;
    float* yb   = (float*)py;

    const int ATTN_SMEM = (32 * 128 + 32 * 128 + 128 * PADV + 128 * PADI + 256) * 4;
    cudaFuncSetAttribute(attn_kernel, cudaFuncAttributeMaxDynamicSharedMemorySize,
                         ATTN_SMEM);

    // 1) qkv = BN(conv1x1(x))
    gemm_bn<<<dim3(64, 8, 2), 256>>>(qkv_w, x, qkv_g, qkv_b, qkv_m, qkv_v, qkvb, HID);
    // 2) attention -> y
    attn_kernel<<<dim3(32, 8), 256, ATTN_SMEM>>>(qkvb, yb);
    // 3) y += BN(depthwise3x3(v))
    pe_kernel<<<dim3(512), 256>>>(qkvb, pe_w, pe_g, pe_b, pe_m, pe_v, yb);
    // 4) out = BN(conv1x1(y))
    gemm_bn<<<dim3(64, 4, 2), 256>>>(proj_w, yb, proj_g, proj_b, proj_m, proj_v, out, DIMC);
}